// round 4
// baseline (speedup 1.0000x reference)
#include <cuda_runtime.h>
#include <cstdint>

#define SQ 2048
#define DH 64
#define NBH 24
#define MASKF (-1.0e9f)
#define SCL 0.5f

typedef unsigned long long ull;

// mask dtype flag: 0 = 1-byte bool/uint8, 1 = int32, 2 = float32
__device__ int g_mask_dtype;

// ---- packed f32x2 helpers (sm_100+ PTX; ptxas never emits FFMA2 on its own) ----
__device__ __forceinline__ ull pk2(float x) {
    ull r; asm("mov.b64 %0, {%1, %1};" : "=l"(r) : "f"(x)); return r;
}
__device__ __forceinline__ void fma2(ull& d, ull a, ull b) {
    asm("fma.rn.f32x2 %0, %1, %2, %0;" : "+l"(d) : "l"(a), "l"(b));
}
__device__ __forceinline__ float2 unpk(ull v) {
    float2 r; asm("mov.b64 {%0, %1}, %2;" : "=f"(r.x), "=f"(r.y) : "l"(v)); return r;
}

// =====================================================================
// Kernel 0: detect mask dtype from its byte pattern (1 warp, 256 bytes)
//   float32 1.0f = [00 00 80 3F] -> some byte >= 2          -> flag 2
//   uint8   1    = [01] at arbitrary offsets                 -> flag 0
//   int32   1    = [01 00 00 00] (nonzero only at j%4==0)    -> flag 1
// =====================================================================
__global__ void detect_mask_kernel(const unsigned char* __restrict__ m) {
    const int t = threadIdx.x;
    ull v = ((const ull*)m)[t];          // 32 threads * 8 bytes = 256 bytes
    int ge2 = 0, off = 0;
    #pragma unroll
    for (int i = 0; i < 8; ++i) {
        unsigned char b = (unsigned char)((v >> (8 * i)) & 0xFF);
        const int j = t * 8 + i;
        if (b >= 2) ge2 = 1;
        if ((j & 3) && b) off = 1;
    }
    ge2 = __any_sync(0xFFFFFFFFu, ge2);
    off = __any_sync(0xFFFFFFFFu, off);
    if (t == 0) g_mask_dtype = ge2 ? 2 : (off ? 0 : 1);
}

// =====================================================================
// Kernel 1: scores = scale * Q @ K^T, masked -> written raw to attn buf
// Tile 128x128, full D=64 in smem (d-major layout for conflict-free LDS)
// =====================================================================
__global__ __launch_bounds__(256, 2)
void qk_scores_kernel(const float* __restrict__ q, const float* __restrict__ k,
                      const void* __restrict__ mask,
                      float* __restrict__ scores) {
    extern __shared__ float sm[];
    float* Qs = sm;              // [64][128] d-major
    float* Ks = sm + 64 * 128;   // [64][128] d-major

    const int t  = threadIdx.x;
    const int bh = blockIdx.z;
    const int i0 = blockIdx.y * 128;
    const int j0 = blockIdx.x * 128;

    const float* Qg = q + ((size_t)bh * SQ + i0) * DH;
    const float* Kg = k + ((size_t)bh * SQ + j0) * DH;

    // ---- transpose-fill via 4x4 register blocks (coalesced LDG, STS.128) ----
    {
        const int d4 = (t & 15) * 4;
        const int rb = (t >> 4) * 4;
        #pragma unroll
        for (int p = 0; p < 2; ++p) {
            const int r0 = rb + 64 * p;
            float rq[4][4], rk[4][4];
            #pragma unroll
            for (int i = 0; i < 4; ++i) {
                float4 a = *(const float4*)(Qg + (size_t)(r0 + i) * DH + d4);
                rq[i][0] = a.x; rq[i][1] = a.y; rq[i][2] = a.z; rq[i][3] = a.w;
                float4 b = *(const float4*)(Kg + (size_t)(r0 + i) * DH + d4);
                rk[i][0] = b.x; rk[i][1] = b.y; rk[i][2] = b.z; rk[i][3] = b.w;
            }
            #pragma unroll
            for (int u = 0; u < 4; ++u) {
                *(float4*)&Qs[(d4 + u) * 128 + r0] =
                    make_float4(rq[0][u], rq[1][u], rq[2][u], rq[3][u]);
                *(float4*)&Ks[(d4 + u) * 128 + r0] =
                    make_float4(rk[0][u], rk[1][u], rk[2][u], rk[3][u]);
            }
        }
    }
    __syncthreads();

    const int ty = t >> 4;   // row group: rows ty*8 .. ty*8+7
    const int tx = t & 15;   // col pairs: cols 2*tx + 32*jj (+0/1)

    ull acc[8][4];
    #pragma unroll
    for (int i = 0; i < 8; ++i)
        #pragma unroll
        for (int j = 0; j < 4; ++j) acc[i][j] = 0ULL;

    #pragma unroll 4
    for (int d = 0; d < 64; ++d) {
        const float* qa = &Qs[d * 128 + ty * 8];
        float4 a0 = *(const float4*)qa;
        float4 a1 = *(const float4*)(qa + 4);
        ull pa[8];
        pa[0] = pk2(a0.x); pa[1] = pk2(a0.y); pa[2] = pk2(a0.z); pa[3] = pk2(a0.w);
        pa[4] = pk2(a1.x); pa[5] = pk2(a1.y); pa[6] = pk2(a1.z); pa[7] = pk2(a1.w);
        const ull* kb = (const ull*)&Ks[d * 128];
        ull b0 = kb[tx], b1 = kb[tx + 16], b2 = kb[tx + 32], b3 = kb[tx + 48];
        #pragma unroll
        for (int ii = 0; ii < 8; ++ii) {
            fma2(acc[ii][0], pa[ii], b0);
            fma2(acc[ii][1], pa[ii], b1);
            fma2(acc[ii][2], pa[ii], b2);
            fma2(acc[ii][3], pa[ii], b3);
        }
    }

    // ---- epilogue: scale + mask (dtype-dispatched), store raw masked scores ----
    const int mf = g_mask_dtype;
    const unsigned char* m8 = (const unsigned char*)mask;
    const int*           m32 = (const int*)mask;
    const float*         mfp = (const float*)mask;

    #pragma unroll
    for (int ii = 0; ii < 8; ++ii) {
        const int row = i0 + ty * 8 + ii;
        const size_t mbase = ((size_t)bh * SQ + row) * SQ + j0;
        float* orow = scores + mbase;
        #pragma unroll
        for (int jj = 0; jj < 4; ++jj) {
            const int col = 2 * tx + 32 * jj;
            float2 s = unpk(acc[ii][jj]);
            bool mx, my;
            if (mf == 0) {
                uchar2 m = *(const uchar2*)(m8 + mbase + col);
                mx = (m.x != 0); my = (m.y != 0);
            } else if (mf == 1) {
                int2 m = *(const int2*)(m32 + mbase + col);
                mx = (m.x != 0); my = (m.y != 0);
            } else {
                float2 m = *(const float2*)(mfp + mbase + col);
                mx = (m.x != 0.0f); my = (m.y != 0.0f);
            }
            float2 o;
            o.x = mx ? MASKF : SCL * s.x;
            o.y = my ? MASKF : SCL * s.y;
            *(float2*)(orow + col) = o;
        }
    }
}

// =====================================================================
// Kernel 2: in-place row softmax over last dim (2048)
// =====================================================================
__global__ __launch_bounds__(256)
void softmax_kernel(float* __restrict__ scores) {
    __shared__ float red[8];
    float* p = scores + (size_t)blockIdx.x * SQ;
    const int t = threadIdx.x;

    float4 v0 = *(const float4*)(p + 4 * t);
    float4 v1 = *(const float4*)(p + 4 * t + 1024);

    float m = fmaxf(fmaxf(fmaxf(v0.x, v0.y), fmaxf(v0.z, v0.w)),
                    fmaxf(fmaxf(v1.x, v1.y), fmaxf(v1.z, v1.w)));
    #pragma unroll
    for (int o = 16; o; o >>= 1) m = fmaxf(m, __shfl_xor_sync(0xFFFFFFFFu, m, o));
    if ((t & 31) == 0) red[t >> 5] = m;
    __syncthreads();
    float mm = red[0];
    #pragma unroll
    for (int w = 1; w < 8; ++w) mm = fmaxf(mm, red[w]);
    __syncthreads();

    v0.x = __expf(v0.x - mm); v0.y = __expf(v0.y - mm);
    v0.z = __expf(v0.z - mm); v0.w = __expf(v0.w - mm);
    v1.x = __expf(v1.x - mm); v1.y = __expf(v1.y - mm);
    v1.z = __expf(v1.z - mm); v1.w = __expf(v1.w - mm);

    float s = (v0.x + v0.y) + (v0.z + v0.w) + (v1.x + v1.y) + (v1.z + v1.w);
    #pragma unroll
    for (int o = 16; o; o >>= 1) s += __shfl_xor_sync(0xFFFFFFFFu, s, o);
    if ((t & 31) == 0) red[t >> 5] = s;
    __syncthreads();
    float ss = red[0];
    #pragma unroll
    for (int w = 1; w < 8; ++w) ss += red[w];

    const float inv = 1.0f / ss;
    v0.x *= inv; v0.y *= inv; v0.z *= inv; v0.w *= inv;
    v1.x *= inv; v1.y *= inv; v1.z *= inv; v1.w *= inv;
    *(float4*)(p + 4 * t) = v0;
    *(float4*)(p + 4 * t + 1024) = v1;
}

// =====================================================================
// Kernel 3: context = attn @ V    (tile 128 rows x 64 cols, BK=64)
// =====================================================================
__global__ __launch_bounds__(256, 2)
void av_kernel(const float* __restrict__ attn, const float* __restrict__ v,
               float* __restrict__ ctx) {
    extern __shared__ float sm[];
    float* As = sm;              // [64][128] kk-major (transposed attn tile)
    float* Vs = sm + 64 * 128;   // [64][64]  natural

    const int t  = threadIdx.x;
    const int bh = blockIdx.y;
    const int i0 = blockIdx.x * 128;

    const float* Ag = attn + ((size_t)bh * SQ + i0) * SQ;
    const float* Vg = v + (size_t)bh * SQ * DH;

    const int ty = t >> 4;  // rows ty*8..+7
    const int tx = t & 15;  // cols 2*tx + 32*jj
    const int c4 = (t & 15) * 4;
    const int rb = (t >> 4) * 4;

    ull acc[8][2];
    #pragma unroll
    for (int i = 0; i < 8; ++i) { acc[i][0] = 0ULL; acc[i][1] = 0ULL; }

    for (int c = 0; c < SQ / 64; ++c) {
        // transpose-fill attn tile -> As[kk][row]
        #pragma unroll
        for (int p = 0; p < 2; ++p) {
            const int r0 = rb + 64 * p;
            float ra[4][4];
            #pragma unroll
            for (int i = 0; i < 4; ++i) {
                float4 a = *(const float4*)(Ag + (size_t)(r0 + i) * SQ + c * 64 + c4);
                ra[i][0] = a.x; ra[i][1] = a.y; ra[i][2] = a.z; ra[i][3] = a.w;
            }
            #pragma unroll
            for (int u = 0; u < 4; ++u)
                *(float4*)&As[(c4 + u) * 128 + r0] =
                    make_float4(ra[0][u], ra[1][u], ra[2][u], ra[3][u]);
        }
        // V tile natural
        #pragma unroll
        for (int i = 0; i < 4; ++i) {
            const int kk = (t >> 4) + 16 * i;
            *(float4*)&Vs[kk * 64 + c4] =
                *(const float4*)(Vg + (size_t)(c * 64 + kk) * DH + c4);
        }
        __syncthreads();

        #pragma unroll 4
        for (int kk = 0; kk < 64; ++kk) {
            const float* aa = &As[kk * 128 + ty * 8];
            float4 a0 = *(const float4*)aa;
            float4 a1 = *(const float4*)(aa + 4);
            ull pa[8];
            pa[0] = pk2(a0.x); pa[1] = pk2(a0.y); pa[2] = pk2(a0.z); pa[3] = pk2(a0.w);
            pa[4] = pk2(a1.x); pa[5] = pk2(a1.y); pa[6] = pk2(a1.z); pa[7] = pk2(a1.w);
            const ull* vb = (const ull*)&Vs[kk * 64];
            ull b0 = vb[tx], b1 = vb[tx + 16];
            #pragma unroll
            for (int ii = 0; ii < 8; ++ii) {
                fma2(acc[ii][0], pa[ii], b0);
                fma2(acc[ii][1], pa[ii], b1);
            }
        }
        __syncthreads();
    }

    #pragma unroll
    for (int ii = 0; ii < 8; ++ii) {
        float* orow = ctx + ((size_t)bh * SQ + i0 + ty * 8 + ii) * DH;
        #pragma unroll
        for (int jj = 0; jj < 2; ++jj) {
            float2 o = unpk(acc[ii][jj]);
            *(float2*)(orow + 2 * tx + 32 * jj) = o;
        }
    }
}

// =====================================================================
extern "C" void kernel_launch(void* const* d_in, const int* in_sizes, int n_in,
                              void* d_out, int out_size) {
    const float* q = (const float*)d_in[0];
    const float* k = (const float*)d_in[1];
    const float* v = (const float*)d_in[2];
    const void*  mask = d_in[3];

    float* ctx  = (float*)d_out;                              // [24, 2048, 64]
    float* attn = (float*)d_out + (size_t)NBH * SQ * DH;      // [24, 2048, 2048]

    cudaFuncSetAttribute(qk_scores_kernel,
                         cudaFuncAttributeMaxDynamicSharedMemorySize, 65536);
    cudaFuncSetAttribute(av_kernel,
                         cudaFuncAttributeMaxDynamicSharedMemorySize, 49152);

    detect_mask_kernel<<<1, 32>>>((const unsigned char*)mask);

    dim3 g1(SQ / 128, SQ / 128, NBH);
    qk_scores_kernel<<<g1, 256, 65536>>>(q, k, mask, attn);

    softmax_kernel<<<NBH * SQ, 256>>>(attn);

    dim3 g3(SQ / 128, NBH);
    av_kernel<<<g3, 256, 49152>>>(attn, v, ctx);
}